// round 5
// baseline (speedup 1.0000x reference)
#include <cuda_runtime.h>
#include <cuda_bf16.h>
#include <cstdint>

// Problem constants
#define B_   32
#define C_   64
#define HW_  1024
#define N_   32768          // B*H*W
#define K_   1024
#define TM   128            // points per block tile
#define NT   128            // codes per block tile (K-split slice)

// ---------------------------------------------------------------------------
// Scratch (no cudaMalloc allowed)
// ---------------------------------------------------------------------------
__device__ unsigned short g_xsplit[3u * N_ * C_];   // bf16 splits of z, [s][n][c]
__device__ unsigned short g_csplit[3u * K_ * C_];   // bf16 splits of cb, [s][k][c]
__device__ float g_hn[K_];                          // 0.5*||c_k||^2
__device__ unsigned long long g_best[N_];           // packed (monotone dist | idx)

// Monotone float->uint mapping (preserves total order incl. negatives)
__device__ __forceinline__ unsigned int fkey(float f) {
    unsigned int u = __float_as_uint(f);
    return (u & 0x80000000u) ? ~u : (u | 0x80000000u);
}

__device__ __forceinline__ unsigned int smem_u32(const void* p) {
    unsigned int a;
    asm("{ .reg .u64 t; cvta.to.shared.u64 t, %1; cvt.u32.u64 %0, t; }"
        : "=r"(a) : "l"(p));
    return a;
}

// ---------------------------------------------------------------------------
// Init: g_best = +inf key
// ---------------------------------------------------------------------------
__global__ void init_kernel() {
    int i = blockIdx.x * blockDim.x + threadIdx.x;
    g_best[i] = 0xFFFFFFFFFFFFFFFFull;
}

// ---------------------------------------------------------------------------
// Prep z: 3-term bf16 split, point-major rows [n][c]. 256 blocks x 256 thr.
// ---------------------------------------------------------------------------
__global__ __launch_bounds__(256)
void prep_z_kernel(const float* __restrict__ z) {
    __shared__ float xs[C_ * TM];      // [c][m]
    const int tid = threadIdx.x;
    const int n0  = blockIdx.x * TM;
    const int b   = n0 / HW_;
    const int hw0 = n0 % HW_;
    const float* zb = z + (size_t)b * C_ * HW_ + hw0;

    {
        int m4 = (tid & 31) * 4;
        int c0 = tid >> 5;
#pragma unroll
        for (int cc = 0; cc < 8; ++cc) {
            int c = c0 + cc * 8;
            *(float4*)&xs[c * TM + m4] = *(const float4*)&zb[c * HW_ + m4];
        }
    }
    __syncthreads();

    if (tid < TM) {
        const int m = tid;
        const size_t nrow = (size_t)(n0 + m) * C_;
#pragma unroll
        for (int c0 = 0; c0 < C_; c0 += 8) {
            uint4 p1, p2, p3;
            unsigned short* s1 = (unsigned short*)&p1;
            unsigned short* s2 = (unsigned short*)&p2;
            unsigned short* s3 = (unsigned short*)&p3;
#pragma unroll
            for (int j = 0; j < 8; ++j) {
                float x = xs[(c0 + j) * TM + m];
                __nv_bfloat16 b1 = __float2bfloat16(x);
                float r = x - __bfloat162float(b1);
                __nv_bfloat16 b2 = __float2bfloat16(r);
                float r2 = r - __bfloat162float(b2);
                __nv_bfloat16 b3 = __float2bfloat16(r2);
                s1[j] = __bfloat16_as_ushort(b1);
                s2[j] = __bfloat16_as_ushort(b2);
                s3[j] = __bfloat16_as_ushort(b3);
            }
            *(uint4*)&g_xsplit[0u * N_ * C_ + nrow + c0] = p1;
            *(uint4*)&g_xsplit[1u * N_ * C_ + nrow + c0] = p2;
            *(uint4*)&g_xsplit[2u * N_ * C_ + nrow + c0] = p3;
        }
    }
}

// ---------------------------------------------------------------------------
// Prep codebook: splits + half norms. 8 blocks x 128 threads (1 row/thread).
// ---------------------------------------------------------------------------
__global__ __launch_bounds__(128)
void prep_cb_kernel(const float* __restrict__ cb) {
    int k = blockIdx.x * 128 + threadIdx.x;          // 0..1023
    const size_t krow = (size_t)k * C_;
    float s = 0.f;
#pragma unroll
    for (int c0 = 0; c0 < C_; c0 += 8) {
        float4 va = *(const float4*)&cb[krow + c0];
        float4 vb = *(const float4*)&cb[krow + c0 + 4];
        float xv[8] = {va.x, va.y, va.z, va.w, vb.x, vb.y, vb.z, vb.w};
        uint4 p1, p2, p3;
        unsigned short* s1 = (unsigned short*)&p1;
        unsigned short* s2 = (unsigned short*)&p2;
        unsigned short* s3 = (unsigned short*)&p3;
#pragma unroll
        for (int j = 0; j < 8; ++j) {
            float x = xv[j];
            s += x * x;
            __nv_bfloat16 b1 = __float2bfloat16(x);
            float r = x - __bfloat162float(b1);
            __nv_bfloat16 b2 = __float2bfloat16(r);
            float r2 = r - __bfloat162float(b2);
            __nv_bfloat16 b3 = __float2bfloat16(r2);
            s1[j] = __bfloat16_as_ushort(b1);
            s2[j] = __bfloat16_as_ushort(b2);
            s3[j] = __bfloat16_as_ushort(b3);
        }
        *(uint4*)&g_csplit[0u * K_ * C_ + krow + c0] = p1;
        *(uint4*)&g_csplit[1u * K_ * C_ + krow + c0] = p2;
        *(uint4*)&g_csplit[2u * K_ * C_ + krow + c0] = p3;
    }
    g_hn[k] = 0.5f * s;
}

// ---------------------------------------------------------------------------
// Main: one block = 128 points x 128 codes via mma.sync bf16 3-split.
// 2048 blocks, 256 threads (8 warps), 2 CTAs/SM.
// smem: A splits 3x16KB @0, B splits 3x16KB @49152, hn[128] @98304.
// Tiles stored [row][64c] bf16, 128B/row, chunk^(row&7) 16B swizzle.
// ---------------------------------------------------------------------------
#define SA_OFF   0
#define SB_OFF   49152
#define SHN_OFF  98304
#define SMEM_SZ  (98304 + 512)

__global__ __launch_bounds__(256, 2)
void vq_kernel() {
    extern __shared__ char smem[];
    const unsigned int sbase = smem_u32(smem);
    const int tid  = threadIdx.x;
    const int wid  = tid >> 5;
    const int lane = tid & 31;

    const int tile = blockIdx.x >> 3;          // point tile 0..255
    const int ks   = blockIdx.x & 7;           // code slice 0..7
    const int n0   = tile * TM;

    // ---- stage tiles gmem -> smem with 16B-chunk XOR swizzle ----
    {
        const uint4* srcA = (const uint4*)(g_xsplit + (size_t)n0 * C_);
        const uint4* srcB = (const uint4*)(g_csplit + (size_t)ks * NT * C_);
        const unsigned int strideA = (N_ * C_) / 8;   // uint4 per split
        const unsigned int strideB = (K_ * C_) / 8;
#pragma unroll
        for (int s = 0; s < 3; ++s) {
#pragma unroll
            for (int i = 0; i < 4; ++i) {
                int idx  = tid + i * 256;             // 0..1023 16B chunks
                int row  = idx >> 3;
                int chk  = idx & 7;
                int sw   = row * 128 + ((chk ^ (row & 7)) * 16);
                *(uint4*)(smem + SA_OFF + s * 16384 + sw) = srcA[s * strideA + idx];
                *(uint4*)(smem + SB_OFF + s * 16384 + sw) = srcB[s * strideB + idx];
            }
        }
        if (tid < NT) *(float*)(smem + SHN_OFF + tid * 4) = g_hn[ks * NT + tid];
    }
    __syncthreads();

    // ---- warp tiling: M = (wid&3)*32 .. +32, N = (wid>>2)*64 .. +64 ----
    const int mrow0 = (wid & 3) * 32;
    const int ncol0 = (wid >> 2) * 64;

    // ldmatrix per-thread row pieces (row&7 == lane&7 for all our rows)
    const int q   = lane >> 3;                 // matrix id within x4
    const int rl  = lane & 7;                  // row-within-8
    // A quadrants: q0:(r0-7,k0-7) q1:(r8-15,k0-7) q2:(r0-7,k8-15) q3:(r8-15,k8-15)
    const int arow = (q & 1) * 8 + rl;
    const int akhalf = q >> 1;
    // B quadrants: q0:(n0-7,k0-7) q1:(n0-7,k8-15) q2:(n8-15,k0-7) q3:(n8-15,k8-15)
    const int brow = (q >> 1) * 8 + rl;
    const int bkhalf = q & 1;

    float acc[2][8][4];
#pragma unroll
    for (int mt = 0; mt < 2; ++mt)
#pragma unroll
        for (int nt = 0; nt < 8; ++nt)
#pragma unroll
            for (int e = 0; e < 4; ++e) acc[mt][nt][e] = 0.f;

    const int pa[6] = {0, 0, 1, 0, 1, 2};
    const int pb[6] = {0, 1, 0, 2, 1, 0};

#pragma unroll
    for (int p = 0; p < 6; ++p) {
        const unsigned int abase = sbase + SA_OFF + pa[p] * 16384;
        const unsigned int bbase = sbase + SB_OFF + pb[p] * 16384;
#pragma unroll
        for (int kc = 0; kc < 4; ++kc) {
            // A fragments for 2 m16 tiles
            unsigned int af[2][4];
#pragma unroll
            for (int mt = 0; mt < 2; ++mt) {
                int row = mrow0 + mt * 16 + arow;
                unsigned int addr = abase + row * 128
                                  + (((kc * 2 + akhalf) ^ rl) * 16);
                asm volatile("ldmatrix.sync.aligned.m8n8.x4.shared.b16 "
                             "{%0,%1,%2,%3}, [%4];"
                             : "=r"(af[mt][0]), "=r"(af[mt][1]),
                               "=r"(af[mt][2]), "=r"(af[mt][3])
                             : "r"(addr));
            }
            // B fragments for 4 n16 groups (each = two n8 tiles)
            unsigned int bf[4][4];
#pragma unroll
            for (int nt2 = 0; nt2 < 4; ++nt2) {
                int row = ncol0 + nt2 * 16 + brow;
                unsigned int addr = bbase + row * 128
                                  + (((kc * 2 + bkhalf) ^ rl) * 16);
                asm volatile("ldmatrix.sync.aligned.m8n8.x4.shared.b16 "
                             "{%0,%1,%2,%3}, [%4];"
                             : "=r"(bf[nt2][0]), "=r"(bf[nt2][1]),
                               "=r"(bf[nt2][2]), "=r"(bf[nt2][3])
                             : "r"(addr));
            }
            // 16 mma
#pragma unroll
            for (int mt = 0; mt < 2; ++mt) {
#pragma unroll
                for (int nt = 0; nt < 8; ++nt) {
                    int nt2 = nt >> 1, hi = nt & 1;
                    asm volatile(
                        "mma.sync.aligned.m16n8k16.row.col.f32.bf16.bf16.f32 "
                        "{%0,%1,%2,%3}, {%4,%5,%6,%7}, {%8,%9}, {%0,%1,%2,%3};"
                        : "+f"(acc[mt][nt][0]), "+f"(acc[mt][nt][1]),
                          "+f"(acc[mt][nt][2]), "+f"(acc[mt][nt][3])
                        : "r"(af[mt][0]), "r"(af[mt][1]),
                          "r"(af[mt][2]), "r"(af[mt][3]),
                          "r"(bf[nt2][hi * 2]), "r"(bf[nt2][hi * 2 + 1]));
                }
            }
        }
    }

    // ---- epilogue: score = 0.5||c||^2 - x.c ; per-row argmin ----
    // lane layout: c0,c1 -> row lane/4,   cols (lane&3)*2 + {0,1}
    //              c2,c3 -> row lane/4+8, same cols
    const float* shn = (const float*)(smem + SHN_OFF);
    float bv[2][2];
    int   bi[2][2];
#pragma unroll
    for (int mt = 0; mt < 2; ++mt)
#pragma unroll
        for (int h = 0; h < 2; ++h) { bv[mt][h] = 3.4e38f; bi[mt][h] = 0; }

#pragma unroll
    for (int nt = 0; nt < 8; ++nt) {
        int colb = ncol0 + nt * 8 + (lane & 3) * 2;
        float h0 = shn[colb], h1 = shn[colb + 1];
#pragma unroll
        for (int mt = 0; mt < 2; ++mt) {
#pragma unroll
            for (int h = 0; h < 2; ++h) {
                float s0 = h0 - acc[mt][nt][h * 2 + 0];
                float s1 = h1 - acc[mt][nt][h * 2 + 1];
                if (s0 < bv[mt][h]) { bv[mt][h] = s0; bi[mt][h] = colb; }
                if (s1 < bv[mt][h]) { bv[mt][h] = s1; bi[mt][h] = colb + 1; }
            }
        }
    }

    // reduce across the 4 lanes sharing each row (xor 1, 2)
#pragma unroll
    for (int mt = 0; mt < 2; ++mt) {
#pragma unroll
        for (int h = 0; h < 2; ++h) {
#pragma unroll
            for (int off = 1; off <= 2; off <<= 1) {
                float ov = __shfl_xor_sync(0xffffffffu, bv[mt][h], off);
                int   oi = __shfl_xor_sync(0xffffffffu, bi[mt][h], off);
                if (ov < bv[mt][h] || (ov == bv[mt][h] && oi < bi[mt][h])) {
                    bv[mt][h] = ov; bi[mt][h] = oi;
                }
            }
        }
    }

    if ((lane & 3) == 0) {
#pragma unroll
        for (int mt = 0; mt < 2; ++mt) {
#pragma unroll
            for (int h = 0; h < 2; ++h) {
                int row = mrow0 + mt * 16 + (lane >> 2) + 8 * h;
                unsigned long long key =
                    ((unsigned long long)fkey(bv[mt][h]) << 32)
                    | (unsigned int)(ks * NT + bi[mt][h]);
                atomicMin(&g_best[n0 + row], key);
            }
        }
    }
}

// ---------------------------------------------------------------------------
// Finalize: 512 blocks x 256 threads, 64 points each. Gather + write outputs.
// ---------------------------------------------------------------------------
#define TF 64
__global__ __launch_bounds__(256)
void finalize_kernel(const float* __restrict__ cb, float* __restrict__ out) {
    __shared__ float scodes[TF * 65];
    __shared__ int   sidx[TF];

    const int tid = threadIdx.x;
    const int n0  = blockIdx.x * TF;
    const int b   = n0 / HW_;
    const int hw0 = n0 % HW_;

    if (tid < TF) {
        unsigned long long key = g_best[n0 + tid];
        int idx = (int)(unsigned int)(key & 0xFFFFFFFFull);
        sidx[tid] = idx;
        out[(size_t)B_ * C_ * HW_ + n0 + tid] = (float)idx;
    }
    __syncthreads();

    {
        int c4 = (tid & 15) * 4;
        int m0 = tid >> 4;                      // 0..15
#pragma unroll
        for (int pass = 0; pass < 4; ++pass) {
            int m = m0 + pass * 16;
            int row = sidx[m];
            float4 v = *(const float4*)&cb[row * C_ + c4];
            scodes[m * 65 + c4 + 0] = v.x;
            scodes[m * 65 + c4 + 1] = v.y;
            scodes[m * 65 + c4 + 2] = v.z;
            scodes[m * 65 + c4 + 3] = v.w;
        }
    }
    __syncthreads();

    {
        int m  = tid & 63;
        int ch = tid >> 6;                      // 0..3
        float* ob = out + (size_t)b * C_ * HW_ + hw0;
#pragma unroll
        for (int j = 0; j < 16; ++j) {
            int c = ch * 16 + j;
            ob[c * HW_ + m] = scodes[m * 65 + c];
        }
    }
}

// ---------------------------------------------------------------------------
extern "C" void kernel_launch(void* const* d_in, const int* in_sizes, int n_in,
                              void* d_out, int out_size) {
    const float* z  = (const float*)d_in[0];
    const float* cb = (const float*)d_in[1];
    float* out = (float*)d_out;
    (void)in_sizes; (void)n_in; (void)out_size;

    cudaFuncSetAttribute(vq_kernel,
                         cudaFuncAttributeMaxDynamicSharedMemorySize, SMEM_SZ);

    init_kernel<<<64, 512>>>();
    prep_z_kernel<<<256, 256>>>(z);
    prep_cb_kernel<<<8, 128>>>(cb);
    vq_kernel<<<2048, 256, SMEM_SZ>>>();
    finalize_kernel<<<512, 256>>>(cb, out);
}

// round 7
// speedup vs baseline: 1.5208x; 1.5208x over previous
#include <cuda_runtime.h>
#include <cuda_bf16.h>
#include <cstdint>

// Problem constants
#define B_   32
#define C_   64
#define HW_  1024
#define N_   32768          // B*H*W
#define K_   1024
#define TM   128            // points per block tile
#define NT   128            // codes per block tile (one slice)
#define TK   128

// ---------------------------------------------------------------------------
// Scratch (no cudaMalloc allowed)
// ---------------------------------------------------------------------------
__device__ unsigned short g_xsplit[3u * N_ * C_];   // bf16 splits of z, [s][n][c]
__device__ unsigned short g_csplit[3u * K_ * C_];   // bf16 splits of cb, [s][k][c]
__device__ float g_cbT[C_ * K_];                    // transposed codebook [c][k]
__device__ float g_hn[K_];                          // 0.5*||c_k||^2
__device__ unsigned long long g_best[N_];           // packed (monotone dist | idx)

// Monotone float->uint mapping (preserves total order incl. negatives)
__device__ __forceinline__ unsigned int fkey(float f) {
    unsigned int u = __float_as_uint(f);
    return (u & 0x80000000u) ? ~u : (u | 0x80000000u);
}

__device__ __forceinline__ unsigned int smem_u32(const void* p) {
    unsigned int a;
    asm("{ .reg .u64 t; cvta.to.shared.u64 t, %1; cvt.u32.u64 %0, t; }"
        : "=r"(a) : "l"(p));
    return a;
}

// ---------------------------------------------------------------------------
// Init: g_best = +inf key
// ---------------------------------------------------------------------------
__global__ void init_kernel() {
    int i = blockIdx.x * blockDim.x + threadIdx.x;
    g_best[i] = 0xFFFFFFFFFFFFFFFFull;
}

// ---------------------------------------------------------------------------
// Prep z: 3-term bf16 split, point-major rows [n][c]. 256 blocks x 256 thr.
// ---------------------------------------------------------------------------
__global__ __launch_bounds__(256)
void prep_z_kernel(const float* __restrict__ z) {
    __shared__ float xs[C_ * TM];      // [c][m]
    const int tid = threadIdx.x;
    const int n0  = blockIdx.x * TM;
    const int b   = n0 / HW_;
    const int hw0 = n0 % HW_;
    const float* zb = z + (size_t)b * C_ * HW_ + hw0;

    {
        int m4 = (tid & 31) * 4;
        int c0 = tid >> 5;
#pragma unroll
        for (int cc = 0; cc < 8; ++cc) {
            int c = c0 + cc * 8;
            *(float4*)&xs[c * TM + m4] = *(const float4*)&zb[c * HW_ + m4];
        }
    }
    __syncthreads();

    if (tid < TM) {
        const int m = tid;
        const size_t nrow = (size_t)(n0 + m) * C_;
#pragma unroll
        for (int c0 = 0; c0 < C_; c0 += 8) {
            uint4 p1, p2, p3;
            unsigned short* s1 = (unsigned short*)&p1;
            unsigned short* s2 = (unsigned short*)&p2;
            unsigned short* s3 = (unsigned short*)&p3;
#pragma unroll
            for (int j = 0; j < 8; ++j) {
                float x = xs[(c0 + j) * TM + m];
                __nv_bfloat16 b1 = __float2bfloat16(x);
                float r = x - __bfloat162float(b1);
                __nv_bfloat16 b2 = __float2bfloat16(r);
                float r2 = r - __bfloat162float(b2);
                __nv_bfloat16 b3 = __float2bfloat16(r2);
                s1[j] = __bfloat16_as_ushort(b1);
                s2[j] = __bfloat16_as_ushort(b2);
                s3[j] = __bfloat16_as_ushort(b3);
            }
            *(uint4*)&g_xsplit[0u * N_ * C_ + nrow + c0] = p1;
            *(uint4*)&g_xsplit[1u * N_ * C_ + nrow + c0] = p2;
            *(uint4*)&g_xsplit[2u * N_ * C_ + nrow + c0] = p3;
        }
    }
}

// ---------------------------------------------------------------------------
// Prep codebook: bf16 splits + fp32 transpose + half norms. 8 x 128.
// ---------------------------------------------------------------------------
__global__ __launch_bounds__(128)
void prep_cb_kernel(const float* __restrict__ cb) {
    int k = blockIdx.x * 128 + threadIdx.x;          // 0..1023
    const size_t krow = (size_t)k * C_;
    float s = 0.f;
#pragma unroll
    for (int c0 = 0; c0 < C_; c0 += 8) {
        float4 va = *(const float4*)&cb[krow + c0];
        float4 vb = *(const float4*)&cb[krow + c0 + 4];
        float xv[8] = {va.x, va.y, va.z, va.w, vb.x, vb.y, vb.z, vb.w};
        uint4 p1, p2, p3;
        unsigned short* s1 = (unsigned short*)&p1;
        unsigned short* s2 = (unsigned short*)&p2;
        unsigned short* s3 = (unsigned short*)&p3;
#pragma unroll
        for (int j = 0; j < 8; ++j) {
            float x = xv[j];
            s += x * x;
            g_cbT[(c0 + j) * K_ + k] = x;
            __nv_bfloat16 b1 = __float2bfloat16(x);
            float r = x - __bfloat162float(b1);
            __nv_bfloat16 b2 = __float2bfloat16(r);
            float r2 = r - __bfloat162float(b2);
            __nv_bfloat16 b3 = __float2bfloat16(r2);
            s1[j] = __bfloat16_as_ushort(b1);
            s2[j] = __bfloat16_as_ushort(b2);
            s3[j] = __bfloat16_as_ushort(b3);
        }
        *(uint4*)&g_csplit[0u * K_ * C_ + krow + c0] = p1;
        *(uint4*)&g_csplit[1u * K_ * C_ + krow + c0] = p2;
        *(uint4*)&g_csplit[2u * K_ * C_ + krow + c0] = p3;
    }
    g_hn[k] = 0.5f * s;
}

// ---------------------------------------------------------------------------
// Hybrid main kernel: 2048 blocks, 256 threads, 2 CTAs/SM.
// Block type = (bid>>2)&1 : 0 = tensor (HMMA) path, slices 0-3
//                           1 = fp32 (FFMA2)  path, slices 4-7
// (bid, bid+148) land on the same SM in wave 1 and get opposite types,
// so both the tensor pipe and the fp32 pipe stay busy on every SM.
// ---------------------------------------------------------------------------
#define SA_OFF   0
#define SB_OFF   49152
#define SHN_OFF  98304
#define SMEM_SZ  (98304 + 512)
// fp32-path layout (same extern smem): xs @0 (32KB), cs @32768 (32KB), hn @65536

__global__ __launch_bounds__(256, 2)
void vq_kernel(const float* __restrict__ z) {
    extern __shared__ char smem[];
    const unsigned int sbase = smem_u32(smem);
    const int tid  = threadIdx.x;
    const int bid  = blockIdx.x;

    const int typ  = (bid >> 2) & 1;
    const unsigned int u = (((unsigned)bid >> 3) << 2) | ((unsigned)bid & 3); // 0..1023
    const int tile = (int)(u >> 2);            // 0..255
    const int slc  = (int)(u & 3);             // 0..3
    const int n0   = tile * TM;

    if (typ == 0) {
        // ================= TENSOR PATH (slices 0-3) =================
        const int wid  = tid >> 5;
        const int lane = tid & 31;
        const int ks   = slc;

        {
            const uint4* srcA = (const uint4*)(g_xsplit + (size_t)n0 * C_);
            const uint4* srcB = (const uint4*)(g_csplit + (size_t)ks * NT * C_);
            const unsigned int strideA = (N_ * C_) / 8;
            const unsigned int strideB = (K_ * C_) / 8;
#pragma unroll
            for (int s = 0; s < 3; ++s) {
#pragma unroll
                for (int i = 0; i < 4; ++i) {
                    int idx  = tid + i * 256;
                    int row  = idx >> 3;
                    int chk  = idx & 7;
                    int sw   = row * 128 + ((chk ^ (row & 7)) * 16);
                    *(uint4*)(smem + SA_OFF + s * 16384 + sw) = srcA[s * strideA + idx];
                    *(uint4*)(smem + SB_OFF + s * 16384 + sw) = srcB[s * strideB + idx];
                }
            }
            if (tid < NT) *(float*)(smem + SHN_OFF + tid * 4) = g_hn[ks * NT + tid];
        }
        __syncthreads();

        const int mrow0 = (wid & 3) * 32;
        const int ncol0 = (wid >> 2) * 64;
        const int q  = lane >> 3;
        const int rl = lane & 7;
        const int arow = (q & 1) * 8 + rl;
        const int akhalf = q >> 1;
        const int brow = (q >> 1) * 8 + rl;
        const int bkhalf = q & 1;

        float acc[2][8][4];
#pragma unroll
        for (int mt = 0; mt < 2; ++mt)
#pragma unroll
            for (int nt = 0; nt < 8; ++nt)
#pragma unroll
                for (int e = 0; e < 4; ++e) acc[mt][nt][e] = 0.f;

        const int pa[6] = {0, 0, 1, 0, 1, 2};
        const int pb[6] = {0, 1, 0, 2, 1, 0};

#pragma unroll
        for (int p = 0; p < 6; ++p) {
            const unsigned int abase = sbase + SA_OFF + pa[p] * 16384;
            const unsigned int bbase = sbase + SB_OFF + pb[p] * 16384;
#pragma unroll
            for (int kc = 0; kc < 4; ++kc) {
                unsigned int af[2][4];
#pragma unroll
                for (int mt = 0; mt < 2; ++mt) {
                    int row = mrow0 + mt * 16 + arow;
                    unsigned int addr = abase + row * 128
                                      + (((kc * 2 + akhalf) ^ rl) * 16);
                    asm volatile("ldmatrix.sync.aligned.m8n8.x4.shared.b16 "
                                 "{%0,%1,%2,%3}, [%4];"
                                 : "=r"(af[mt][0]), "=r"(af[mt][1]),
                                   "=r"(af[mt][2]), "=r"(af[mt][3])
                                 : "r"(addr));
                }
                unsigned int bf[4][4];
#pragma unroll
                for (int nt2 = 0; nt2 < 4; ++nt2) {
                    int row = ncol0 + nt2 * 16 + brow;
                    unsigned int addr = bbase + row * 128
                                      + (((kc * 2 + bkhalf) ^ rl) * 16);
                    asm volatile("ldmatrix.sync.aligned.m8n8.x4.shared.b16 "
                                 "{%0,%1,%2,%3}, [%4];"
                                 : "=r"(bf[nt2][0]), "=r"(bf[nt2][1]),
                                   "=r"(bf[nt2][2]), "=r"(bf[nt2][3])
                                 : "r"(addr));
                }
#pragma unroll
                for (int mt = 0; mt < 2; ++mt) {
#pragma unroll
                    for (int nt = 0; nt < 8; ++nt) {
                        int nt2 = nt >> 1, hi = nt & 1;
                        asm volatile(
                            "mma.sync.aligned.m16n8k16.row.col.f32.bf16.bf16.f32 "
                            "{%0,%1,%2,%3}, {%4,%5,%6,%7}, {%8,%9}, {%0,%1,%2,%3};"
                            : "+f"(acc[mt][nt][0]), "+f"(acc[mt][nt][1]),
                              "+f"(acc[mt][nt][2]), "+f"(acc[mt][nt][3])
                            : "r"(af[mt][0]), "r"(af[mt][1]),
                              "r"(af[mt][2]), "r"(af[mt][3]),
                              "r"(bf[nt2][hi * 2]), "r"(bf[nt2][hi * 2 + 1]));
                    }
                }
            }
        }

        const float* shn = (const float*)(smem + SHN_OFF);
        float bv[2][2];
        int   bi[2][2];
#pragma unroll
        for (int mt = 0; mt < 2; ++mt)
#pragma unroll
            for (int h = 0; h < 2; ++h) { bv[mt][h] = 3.4e38f; bi[mt][h] = 0; }

#pragma unroll
        for (int nt = 0; nt < 8; ++nt) {
            int colb = ncol0 + nt * 8 + (lane & 3) * 2;
            float h0 = shn[colb], h1 = shn[colb + 1];
#pragma unroll
            for (int mt = 0; mt < 2; ++mt) {
#pragma unroll
                for (int h = 0; h < 2; ++h) {
                    float s0 = h0 - acc[mt][nt][h * 2 + 0];
                    float s1 = h1 - acc[mt][nt][h * 2 + 1];
                    if (s0 < bv[mt][h]) { bv[mt][h] = s0; bi[mt][h] = colb; }
                    if (s1 < bv[mt][h]) { bv[mt][h] = s1; bi[mt][h] = colb + 1; }
                }
            }
        }

#pragma unroll
        for (int mt = 0; mt < 2; ++mt) {
#pragma unroll
            for (int h = 0; h < 2; ++h) {
#pragma unroll
                for (int off = 1; off <= 2; off <<= 1) {
                    float ov = __shfl_xor_sync(0xffffffffu, bv[mt][h], off);
                    int   oi = __shfl_xor_sync(0xffffffffu, bi[mt][h], off);
                    if (ov < bv[mt][h] || (ov == bv[mt][h] && oi < bi[mt][h])) {
                        bv[mt][h] = ov; bi[mt][h] = oi;
                    }
                }
            }
        }

        if ((lane & 3) == 0) {
#pragma unroll
            for (int mt = 0; mt < 2; ++mt) {
#pragma unroll
                for (int h = 0; h < 2; ++h) {
                    int row = mrow0 + mt * 16 + (lane >> 2) + 8 * h;
                    unsigned long long key =
                        ((unsigned long long)fkey(bv[mt][h]) << 32)
                        | (unsigned int)(ks * NT + bi[mt][h]);
                    atomicMin(&g_best[n0 + row], key);
                }
            }
        }
    } else {
        // ================= FP32 FFMA2 PATH (slices 4-7) =================
        float* xs  = (float*)smem;                 // [64][128]
        float* cs  = (float*)(smem + 32768);       // [64][128]
        float* hns = (float*)(smem + 65536);       // [128]
        const int ks = 4 + slc;

        const int b   = n0 / HW_;
        const int hw0 = n0 % HW_;
        const float* zb = z + (size_t)b * C_ * HW_ + hw0;

        {
            int m4 = (tid & 31) * 4;
            int c0 = tid >> 5;
#pragma unroll
            for (int cc = 0; cc < 8; ++cc) {
                int c = c0 + cc * 8;
                float4 v = *(const float4*)&zb[c * HW_ + m4];
                v.x = -v.x; v.y = -v.y; v.z = -v.z; v.w = -v.w;
                *(float4*)&xs[c * TM + m4] = v;
                *(float4*)&cs[c * TK + m4] =
                    *(const float4*)&g_cbT[c * K_ + ks * TK + m4];
            }
            if (tid < TK) hns[tid] = g_hn[ks * TK + tid];
        }
        __syncthreads();

        const int tx  = tid & 15;
        const int ty  = tid >> 4;
        const int tx4 = tx * 4, ty4 = ty * 4;

        unsigned long long acc[8][4];
        {
            ulonglong2 ha = *(ulonglong2*)&hns[tx4];
            ulonglong2 hb = *(ulonglong2*)&hns[64 + tx4];
#pragma unroll
            for (int i = 0; i < 8; ++i) {
                acc[i][0] = ha.x; acc[i][1] = ha.y;
                acc[i][2] = hb.x; acc[i][3] = hb.y;
            }
        }

#pragma unroll 4
        for (int c = 0; c < C_; ++c) {
            float4 xa = *(float4*)&xs[c * TM + ty4];
            float4 xb = *(float4*)&xs[c * TM + 64 + ty4];
            ulonglong2 ca  = *(ulonglong2*)&cs[c * TK + tx4];
            ulonglong2 cbp = *(ulonglong2*)&cs[c * TK + 64 + tx4];
            unsigned long long cf0 = ca.x,  cf1 = ca.y;
            unsigned long long cf2 = cbp.x, cf3 = cbp.y;
            float xv[8] = {xa.x, xa.y, xa.z, xa.w, xb.x, xb.y, xb.z, xb.w};
#pragma unroll
            for (int i = 0; i < 8; ++i) {
                unsigned long long xd;
                asm("mov.b64 %0, {%1, %1};"
                    : "=l"(xd) : "r"(__float_as_uint(xv[i])));
                asm("fma.rn.f32x2 %0, %1, %2, %0;" : "+l"(acc[i][0]) : "l"(xd), "l"(cf0));
                asm("fma.rn.f32x2 %0, %1, %2, %0;" : "+l"(acc[i][1]) : "l"(xd), "l"(cf1));
                asm("fma.rn.f32x2 %0, %1, %2, %0;" : "+l"(acc[i][2]) : "l"(xd), "l"(cf2));
                asm("fma.rn.f32x2 %0, %1, %2, %0;" : "+l"(acc[i][3]) : "l"(xd), "l"(cf3));
            }
        }

        const int kbase = ks * TK;
        float bv[8];
        int   bi[8];
#pragma unroll
        for (int i = 0; i < 8; ++i) { bv[i] = 3.4e38f; bi[i] = 0x7fffffff; }
#pragma unroll
        for (int i = 0; i < 8; ++i) {
#pragma unroll
            for (int p = 0; p < 4; ++p) {
                float vlo = __uint_as_float((unsigned int)acc[i][p]);
                float vhi = __uint_as_float((unsigned int)(acc[i][p] >> 32));
                int col = (p < 2) ? (tx4 + 2 * p) : (64 + tx4 + 2 * (p - 2));
                if (vlo < bv[i]) { bv[i] = vlo; bi[i] = kbase + col; }
                if (vhi < bv[i]) { bv[i] = vhi; bi[i] = kbase + col + 1; }
            }
        }

#pragma unroll
        for (int i = 0; i < 8; ++i) {
#pragma unroll
            for (int off = 8; off > 0; off >>= 1) {
                float ov = __shfl_xor_sync(0xffffffffu, bv[i], off, 16);
                int   oi = __shfl_xor_sync(0xffffffffu, bi[i], off, 16);
                if (ov < bv[i] || (ov == bv[i] && oi < bi[i])) { bv[i] = ov; bi[i] = oi; }
            }
        }

        if (tx == 0) {
#pragma unroll
            for (int i = 0; i < 8; ++i) {
                int row = (i < 4) ? (ty4 + i) : (64 + ty4 + (i - 4));
                unsigned long long key =
                    ((unsigned long long)fkey(bv[i]) << 32) | (unsigned int)bi[i];
                atomicMin(&g_best[n0 + row], key);
            }
        }
    }
}

// ---------------------------------------------------------------------------
// Finalize: 512 blocks x 256 threads, 64 points each. Gather + write outputs.
// ---------------------------------------------------------------------------
#define TF 64
__global__ __launch_bounds__(256)
void finalize_kernel(const float* __restrict__ cb, float* __restrict__ out) {
    __shared__ float scodes[TF * 65];
    __shared__ int   sidx[TF];

    const int tid = threadIdx.x;
    const int n0  = blockIdx.x * TF;
    const int b   = n0 / HW_;
    const int hw0 = n0 % HW_;

    if (tid < TF) {
        unsigned long long key = g_best[n0 + tid];
        int idx = (int)(unsigned int)(key & 0xFFFFFFFFull);
        sidx[tid] = idx;
        out[(size_t)B_ * C_ * HW_ + n0 + tid] = (float)idx;
    }
    __syncthreads();

    {
        int c4 = (tid & 15) * 4;
        int m0 = tid >> 4;
#pragma unroll
        for (int pass = 0; pass < 4; ++pass) {
            int m = m0 + pass * 16;
            int row = sidx[m];
            float4 v = *(const float4*)&cb[row * C_ + c4];
            scodes[m * 65 + c4 + 0] = v.x;
            scodes[m * 65 + c4 + 1] = v.y;
            scodes[m * 65 + c4 + 2] = v.z;
            scodes[m * 65 + c4 + 3] = v.w;
        }
    }
    __syncthreads();

    {
        int m  = tid & 63;
        int ch = tid >> 6;
        float* ob = out + (size_t)b * C_ * HW_ + hw0;
#pragma unroll
        for (int j = 0; j < 16; ++j) {
            int c = ch * 16 + j;
            ob[c * HW_ + m] = scodes[m * 65 + c];
        }
    }
}

// ---------------------------------------------------------------------------
extern "C" void kernel_launch(void* const* d_in, const int* in_sizes, int n_in,
                              void* d_out, int out_size) {
    const float* z  = (const float*)d_in[0];
    const float* cb = (const float*)d_in[1];
    float* out = (float*)d_out;
    (void)in_sizes; (void)n_in; (void)out_size;

    cudaFuncSetAttribute(vq_kernel,
                         cudaFuncAttributeMaxDynamicSharedMemorySize, SMEM_SZ);

    init_kernel<<<64, 512>>>();
    prep_z_kernel<<<256, 256>>>(z);
    prep_cb_kernel<<<8, 128>>>(cb);
    vq_kernel<<<2048, 256, SMEM_SZ>>>(z);
    finalize_kernel<<<512, 256>>>(cb, out);
}

// round 8
// speedup vs baseline: 1.5957x; 1.0492x over previous
#include <cuda_runtime.h>
#include <cuda_bf16.h>
#include <cstdint>

// Problem constants
#define B_   32
#define C_   64
#define HW_  1024
#define N_   32768          // B*H*W
#define K_   1024
#define TM   128            // points per block tile
#define NT   128            // codes per block tile (one slice)

// ---------------------------------------------------------------------------
// Scratch (no cudaMalloc allowed)
// ---------------------------------------------------------------------------
__device__ unsigned short g_x1[N_ * C_];      // bf16 round of z, row-major [n][c]
__device__ float          g_xrm[N_ * C_];     // fp32 z, row-major [n][c]
__device__ unsigned short g_c1[K_ * C_];      // bf16 round of cb, [k][c]
__device__ float g_hn[K_];                    // 0.5*||c_k||^2
__device__ float g_xS[N_];                    // sum_i |x_i| per point
__device__ unsigned long long g_best[N_];     // packed (monotone dist | idx)

// Monotone float->uint mapping (preserves total order incl. negatives)
__device__ __forceinline__ unsigned int fkey(float f) {
    unsigned int u = __float_as_uint(f);
    return (u & 0x80000000u) ? ~u : (u | 0x80000000u);
}

__device__ __forceinline__ unsigned int smem_u32(const void* p) {
    unsigned int a;
    asm("{ .reg .u64 t; cvta.to.shared.u64 t, %1; cvt.u32.u64 %0, t; }"
        : "=r"(a) : "l"(p));
    return a;
}

// ---------------------------------------------------------------------------
// Prep z: bf16 round + fp32 row-major copy + sum|x| + g_best init.
// 256 blocks x 256 threads (one block = 128 points).
// ---------------------------------------------------------------------------
__global__ __launch_bounds__(256)
void prep_z_kernel(const float* __restrict__ z) {
    __shared__ float xs[C_ * TM];      // [c][m]
    const int tid = threadIdx.x;
    const int n0  = blockIdx.x * TM;
    const int b   = n0 / HW_;
    const int hw0 = n0 % HW_;
    const float* zb = z + (size_t)b * C_ * HW_ + hw0;

    {
        int m4 = (tid & 31) * 4;
        int c0 = tid >> 5;
#pragma unroll
        for (int cc = 0; cc < 8; ++cc) {
            int c = c0 + cc * 8;
            *(float4*)&xs[c * TM + m4] = *(const float4*)&zb[c * HW_ + m4];
        }
    }
    __syncthreads();

    if (tid < TM) {
        const int m = tid;
        const int n = n0 + m;
        const size_t nrow = (size_t)n * C_;
        float S = 0.f;
#pragma unroll
        for (int c0 = 0; c0 < C_; c0 += 8) {
            uint4 p1;
            unsigned short* s1 = (unsigned short*)&p1;
            float xv[8];
#pragma unroll
            for (int j = 0; j < 8; ++j) {
                float x = xs[(c0 + j) * TM + m];
                xv[j] = x;
                S += fabsf(x);
                s1[j] = __bfloat16_as_ushort(__float2bfloat16(x));
            }
            *(uint4*)&g_x1[nrow + c0] = p1;
            *(float4*)&g_xrm[nrow + c0]     = make_float4(xv[0], xv[1], xv[2], xv[3]);
            *(float4*)&g_xrm[nrow + c0 + 4] = make_float4(xv[4], xv[5], xv[6], xv[7]);
        }
        g_xS[n]   = S;
        g_best[n] = 0xFFFFFFFFFFFFFFFFull;
    }
}

// ---------------------------------------------------------------------------
// Prep codebook: bf16 round + half norms. 8 blocks x 128 threads.
// ---------------------------------------------------------------------------
__global__ __launch_bounds__(128)
void prep_cb_kernel(const float* __restrict__ cb) {
    int k = blockIdx.x * 128 + threadIdx.x;          // 0..1023
    const size_t krow = (size_t)k * C_;
    float s = 0.f;
#pragma unroll
    for (int c0 = 0; c0 < C_; c0 += 8) {
        float4 va = *(const float4*)&cb[krow + c0];
        float4 vb = *(const float4*)&cb[krow + c0 + 4];
        float xv[8] = {va.x, va.y, va.z, va.w, vb.x, vb.y, vb.z, vb.w};
        uint4 p1;
        unsigned short* s1 = (unsigned short*)&p1;
#pragma unroll
        for (int j = 0; j < 8; ++j) {
            float x = xv[j];
            s += x * x;
            s1[j] = __bfloat16_as_ushort(__float2bfloat16(x));
        }
        *(uint4*)&g_c1[krow + c0] = p1;
    }
    g_hn[k] = 0.5f * s;
}

// ---------------------------------------------------------------------------
// Main: one block = 128 points x 128 codes (one slice), bf16 1-product MMA
// as a FILTER with rigorous margin, exact fp32 verify from smem.
// 2048 blocks x 256 threads, 2 CTAs/SM.
// ---------------------------------------------------------------------------
#define SA_OFF   0            // bf16 A tile, swizzled: 16384
#define SB_OFF   16384        // bf16 B tile, swizzled: 16384
#define SX_OFF   32768        // fp32 x [128][65]: 33280
#define SC_OFF   66048        // fp32 c [128][65]: 33280
#define SHN_OFF  99328        // hn slice: 512
#define SXS_OFF  99840        // sum|x|: 512
#define SQC_OFF  100352       // queue count: 16
#define SQ_OFF   100368       // queue: 2048 * 4
#define QCAP     2048
#define SMEM_SZ  (100368 + QCAP * 4)

__global__ __launch_bounds__(256, 2)
void vq_kernel(const float* __restrict__ cb) {
    extern __shared__ char smem[];
    const unsigned int sbase = smem_u32(smem);
    float* xf  = (float*)(smem + SX_OFF);
    float* cf  = (float*)(smem + SC_OFF);
    float* shn = (float*)(smem + SHN_OFF);
    float* sxs = (float*)(smem + SXS_OFF);
    int*   qc  = (int*)(smem + SQC_OFF);
    int*   qu  = (int*)(smem + SQ_OFF);

    const int tid  = threadIdx.x;
    const int wid  = tid >> 5;
    const int lane = tid & 31;
    const int tile = blockIdx.x >> 3;          // 0..255
    const int ks   = blockIdx.x & 7;           // 0..7
    const int n0   = tile * TM;

    // ---- stage bf16 tiles (swizzled) + fp32 tiles (padded 65) ----
    {
        const uint4* srcA = (const uint4*)(g_x1 + (size_t)n0 * C_);
        const uint4* srcB = (const uint4*)(g_c1 + (size_t)ks * NT * C_);
#pragma unroll
        for (int i = 0; i < 4; ++i) {
            int idx = tid + i * 256;           // 0..1023 16B chunks
            int row = idx >> 3;
            int chk = idx & 7;
            int sw  = row * 128 + ((chk ^ (row & 7)) * 16);
            *(uint4*)(smem + SA_OFF + sw) = srcA[idx];
            *(uint4*)(smem + SB_OFF + sw) = srcB[idx];
        }
        const float4* srcX = (const float4*)(g_xrm + (size_t)n0 * C_);
        const float4* srcC = (const float4*)(cb + (size_t)ks * NT * C_);
#pragma unroll
        for (int i = 0; i < 8; ++i) {
            int idx = tid + i * 256;           // 0..2047 float4s
            int row = idx >> 4;
            int c4  = (idx & 15) * 4;
            float4 vx = srcX[idx];
            float4 vc = srcC[idx];
            xf[row * 65 + c4 + 0] = vx.x; xf[row * 65 + c4 + 1] = vx.y;
            xf[row * 65 + c4 + 2] = vx.z; xf[row * 65 + c4 + 3] = vx.w;
            cf[row * 65 + c4 + 0] = vc.x; cf[row * 65 + c4 + 1] = vc.y;
            cf[row * 65 + c4 + 2] = vc.z; cf[row * 65 + c4 + 3] = vc.w;
        }
        if (tid < NT) {
            shn[tid] = g_hn[ks * NT + tid];
            sxs[tid] = g_xS[n0 + tid];
        }
        if (tid == 0) *qc = 0;
    }
    __syncthreads();

    // ---- MMA: single bf16 product, 4 k16 chunks ----
    const int mrow0 = (wid & 3) * 32;
    const int ncol0 = (wid >> 2) * 64;
    const int q  = lane >> 3;
    const int rl = lane & 7;
    const int arow = (q & 1) * 8 + rl;
    const int akhalf = q >> 1;
    const int brow = (q >> 1) * 8 + rl;
    const int bkhalf = q & 1;

    float acc[2][8][4];
#pragma unroll
    for (int mt = 0; mt < 2; ++mt)
#pragma unroll
        for (int nt = 0; nt < 8; ++nt)
#pragma unroll
            for (int e = 0; e < 4; ++e) acc[mt][nt][e] = 0.f;

#pragma unroll
    for (int kc = 0; kc < 4; ++kc) {
        unsigned int af[2][4];
#pragma unroll
        for (int mt = 0; mt < 2; ++mt) {
            int row = mrow0 + mt * 16 + arow;
            unsigned int addr = sbase + SA_OFF + row * 128
                              + (((kc * 2 + akhalf) ^ rl) * 16);
            asm volatile("ldmatrix.sync.aligned.m8n8.x4.shared.b16 "
                         "{%0,%1,%2,%3}, [%4];"
                         : "=r"(af[mt][0]), "=r"(af[mt][1]),
                           "=r"(af[mt][2]), "=r"(af[mt][3])
                         : "r"(addr));
        }
        unsigned int bf[4][4];
#pragma unroll
        for (int nt2 = 0; nt2 < 4; ++nt2) {
            int row = ncol0 + nt2 * 16 + brow;
            unsigned int addr = sbase + SB_OFF + row * 128
                              + (((kc * 2 + bkhalf) ^ rl) * 16);
            asm volatile("ldmatrix.sync.aligned.m8n8.x4.shared.b16 "
                         "{%0,%1,%2,%3}, [%4];"
                         : "=r"(bf[nt2][0]), "=r"(bf[nt2][1]),
                           "=r"(bf[nt2][2]), "=r"(bf[nt2][3])
                         : "r"(addr));
        }
#pragma unroll
        for (int mt = 0; mt < 2; ++mt) {
#pragma unroll
            for (int nt = 0; nt < 8; ++nt) {
                int nt2 = nt >> 1, hi = nt & 1;
                asm volatile(
                    "mma.sync.aligned.m16n8k16.row.col.f32.bf16.bf16.f32 "
                    "{%0,%1,%2,%3}, {%4,%5,%6,%7}, {%8,%9}, {%0,%1,%2,%3};"
                    : "+f"(acc[mt][nt][0]), "+f"(acc[mt][nt][1]),
                      "+f"(acc[mt][nt][2]), "+f"(acc[mt][nt][3])
                    : "r"(af[mt][0]), "r"(af[mt][1]),
                      "r"(af[mt][2]), "r"(af[mt][3]),
                      "r"(bf[nt2][hi * 2]), "r"(bf[nt2][hi * 2 + 1]));
            }
        }
    }

    // ---- approx per-row half-min over this warp's 64 cols ----
    float bv[2][2];
#pragma unroll
    for (int mt = 0; mt < 2; ++mt)
#pragma unroll
        for (int h = 0; h < 2; ++h) bv[mt][h] = 3.4e38f;

#pragma unroll
    for (int nt = 0; nt < 8; ++nt) {
        int colb = ncol0 + nt * 8 + (lane & 3) * 2;
        float h0 = shn[colb], h1 = shn[colb + 1];
#pragma unroll
        for (int mt = 0; mt < 2; ++mt) {
#pragma unroll
            for (int h = 0; h < 2; ++h) {
                float s0 = h0 - acc[mt][nt][h * 2 + 0];
                float s1 = h1 - acc[mt][nt][h * 2 + 1];
                bv[mt][h] = fminf(bv[mt][h], fminf(s0, s1));
            }
        }
    }
#pragma unroll
    for (int mt = 0; mt < 2; ++mt)
#pragma unroll
        for (int h = 0; h < 2; ++h) {
#pragma unroll
            for (int off = 1; off <= 2; off <<= 1)
                bv[mt][h] = fminf(bv[mt][h],
                                  __shfl_xor_sync(0xffffffffu, bv[mt][h], off));
        }

    // ---- thresholds with rigorous margin; queue candidates ----
    // |exact - approx| <= 2^-7*1.002*S + accum slack  (|c_i| < 1, bf16 u=2^-8)
    float T[2][2];
#pragma unroll
    for (int mt = 0; mt < 2; ++mt)
#pragma unroll
        for (int h = 0; h < 2; ++h) {
            int row = mrow0 + mt * 16 + (lane >> 2) + 8 * h;
            T[mt][h] = bv[mt][h] + sxs[row] * 0.0158f + 0.002f;
        }

#pragma unroll
    for (int nt = 0; nt < 8; ++nt) {
        int colb = ncol0 + nt * 8 + (lane & 3) * 2;
        float h0 = shn[colb], h1 = shn[colb + 1];
#pragma unroll
        for (int mt = 0; mt < 2; ++mt) {
#pragma unroll
            for (int h = 0; h < 2; ++h) {
                int row = mrow0 + mt * 16 + (lane >> 2) + 8 * h;
                float s0 = h0 - acc[mt][nt][h * 2 + 0];
                float s1 = h1 - acc[mt][nt][h * 2 + 1];
#pragma unroll
                for (int e = 0; e < 2; ++e) {
                    float s = e ? s1 : s0;
                    int col = colb + e;
                    if (s <= T[mt][h]) {
                        int idx = atomicAdd(qc, 1);
                        if (idx < QCAP) {
                            qu[idx] = (row << 8) | col;
                        } else {
                            // overflow fallback: inline exact eval
                            const float* xr = &xf[row * 65];
                            const float* cr = &cf[col * 65];
                            float sx = shn[col];
#pragma unroll 8
                            for (int c = 0; c < C_; ++c)
                                sx = fmaf(-xr[c], cr[c], sx);
                            unsigned long long key =
                                ((unsigned long long)fkey(sx) << 32)
                                | (unsigned int)(ks * NT + col);
                            atomicMin(&g_best[n0 + row], key);
                        }
                    }
                }
            }
        }
    }
    __syncthreads();

    // ---- exact fp32 verification of queued candidates ----
    int qn = *qc;
    if (qn > QCAP) qn = QCAP;
    for (int i = tid; i < qn; i += 256) {
        int e   = qu[i];
        int row = e >> 8;
        int col = e & 255;
        const float* xr = &xf[row * 65];
        const float* cr = &cf[col * 65];
        float s = shn[col];
#pragma unroll 8
        for (int c = 0; c < C_; ++c)
            s = fmaf(-xr[c], cr[c], s);
        unsigned long long key =
            ((unsigned long long)fkey(s) << 32)
            | (unsigned int)(ks * NT + col);
        atomicMin(&g_best[n0 + row], key);
    }
}

// ---------------------------------------------------------------------------
// Finalize: 512 blocks x 256 threads, 64 points each. float4 output stores.
// ---------------------------------------------------------------------------
#define TF 64
__global__ __launch_bounds__(256)
void finalize_kernel(const float* __restrict__ cb, float* __restrict__ out) {
    __shared__ float scodes[TF * 65];
    __shared__ int   sidx[TF];

    const int tid = threadIdx.x;
    const int n0  = blockIdx.x * TF;
    const int b   = n0 / HW_;
    const int hw0 = n0 % HW_;

    if (tid < TF) {
        unsigned long long key = g_best[n0 + tid];
        int idx = (int)(unsigned int)(key & 0xFFFFFFFFull);
        sidx[tid] = idx;
        out[(size_t)B_ * C_ * HW_ + n0 + tid] = (float)idx;
    }
    __syncthreads();

    // gather winning codebook rows -> smem (pad 65)
    {
#pragma unroll
        for (int i = 0; i < 4; ++i) {
            int idx = tid + i * 256;           // 0..1023 float4s
            int m   = idx >> 4;
            int c4  = (idx & 15) * 4;
            float4 v = *(const float4*)&cb[sidx[m] * C_ + c4];
            scodes[m * 65 + c4 + 0] = v.x;
            scodes[m * 65 + c4 + 1] = v.y;
            scodes[m * 65 + c4 + 2] = v.z;
            scodes[m * 65 + c4 + 3] = v.w;
        }
    }
    __syncthreads();

    // coalesced [B,C,H,W] float4 writes along m
    {
        int m4    = (tid & 15) * 4;
        int cbase = tid >> 4;                  // 0..15
        float* ob = out + (size_t)b * C_ * HW_ + hw0;
#pragma unroll
        for (int j = 0; j < 4; ++j) {
            int c = cbase + j * 16;
            float4 w;
            w.x = scodes[(m4 + 0) * 65 + c];
            w.y = scodes[(m4 + 1) * 65 + c];
            w.z = scodes[(m4 + 2) * 65 + c];
            w.w = scodes[(m4 + 3) * 65 + c];
            *(float4*)&ob[c * HW_ + m4] = w;
        }
    }
}

// ---------------------------------------------------------------------------
extern "C" void kernel_launch(void* const* d_in, const int* in_sizes, int n_in,
                              void* d_out, int out_size) {
    const float* z  = (const float*)d_in[0];
    const float* cb = (const float*)d_in[1];
    float* out = (float*)d_out;
    (void)in_sizes; (void)n_in; (void)out_size;

    cudaFuncSetAttribute(vq_kernel,
                         cudaFuncAttributeMaxDynamicSharedMemorySize, SMEM_SZ);

    prep_z_kernel<<<256, 256>>>(z);
    prep_cb_kernel<<<8, 128>>>(cb);
    vq_kernel<<<2048, 256, SMEM_SZ>>>(cb);
    finalize_kernel<<<512, 256>>>(cb, out);
}